// round 3
// baseline (speedup 1.0000x reference)
#include <cuda_runtime.h>
#include <math.h>

#define NM 1024
#define HH 256
#define WW 256
#define HW 65536
#define OUT_MASKS ((size_t)NM * HW)            // 67108864 floats
#define OUT_KEEP_OFF OUT_MASKS                 // keep[1024]
#define OUT_BOX_OFF (OUT_MASKS + NM)           // boxes[1024*4]

// ---- scratch (no allocations allowed) ----
__device__ int   g_hi[NM];
__device__ int   g_lo[NM];
__device__ int   g_minr[NM];
__device__ int   g_maxr[NM];
__device__ int   g_minc[NM];
__device__ int   g_maxc[NM];
__device__ float g_gated[NM];

// ============================================================
// Kernel 1: per-mask stats (hi/lo threshold counts + bbox)
// One block per mask, 256 threads, float4 coalesced reads.
// ============================================================
__global__ void __launch_bounds__(256) sam_stats_kernel(const float* __restrict__ logits)
{
    const int n = blockIdx.x;
    const float4* __restrict__ p =
        reinterpret_cast<const float4*>(logits + (size_t)n * HW);
    const int tid = threadIdx.x;

    int hi = 0, lo = 0;
    int minr = HH, maxr = -1, minc = WW, maxc = -1;

    // 65536 elems = 16384 float4; 256 threads -> 64 iters
#pragma unroll 8
    for (int it = 0; it < 64; ++it) {
        const int i4 = it * 256 + tid;
        const float4 v = p[i4];
        const int e   = i4 << 2;
        const int row = e >> 8;
        const int col = e & 255;

        const float vs0 = v.x, vs1 = v.y, vs2 = v.z, vs3 = v.w;
        hi += (vs0 > 1.0f) + (vs1 > 1.0f) + (vs2 > 1.0f) + (vs3 > 1.0f);
        lo += (vs0 > -1.0f) + (vs1 > -1.0f) + (vs2 > -1.0f) + (vs3 > -1.0f);

        const bool b0 = vs0 > 0.0f, b1 = vs1 > 0.0f, b2 = vs2 > 0.0f, b3 = vs3 > 0.0f;
        if (b0 | b1 | b2 | b3) {
            minr = min(minr, row);
            maxr = max(maxr, row);
            if (b0) { minc = min(minc, col);     maxc = max(maxc, col);     }
            if (b1) { minc = min(minc, col + 1); maxc = max(maxc, col + 1); }
            if (b2) { minc = min(minc, col + 2); maxc = max(maxc, col + 2); }
            if (b3) { minc = min(minc, col + 3); maxc = max(maxc, col + 3); }
        }
    }

    // warp reduce
#pragma unroll
    for (int o = 16; o > 0; o >>= 1) {
        hi   += __shfl_down_sync(0xFFFFFFFFu, hi, o);
        lo   += __shfl_down_sync(0xFFFFFFFFu, lo, o);
        minr = min(minr, __shfl_down_sync(0xFFFFFFFFu, minr, o));
        maxr = max(maxr, __shfl_down_sync(0xFFFFFFFFu, maxr, o));
        minc = min(minc, __shfl_down_sync(0xFFFFFFFFu, minc, o));
        maxc = max(maxc, __shfl_down_sync(0xFFFFFFFFu, maxc, o));
    }

    __shared__ int s_hi[8], s_lo[8], s_minr[8], s_maxr[8], s_minc[8], s_maxc[8];
    const int w = tid >> 5;
    if ((tid & 31) == 0) {
        s_hi[w] = hi; s_lo[w] = lo;
        s_minr[w] = minr; s_maxr[w] = maxr;
        s_minc[w] = minc; s_maxc[w] = maxc;
    }
    __syncthreads();
    if (tid == 0) {
#pragma unroll
        for (int k = 1; k < 8; ++k) {
            hi += s_hi[k]; lo += s_lo[k];
            minr = min(minr, s_minr[k]); maxr = max(maxr, s_maxr[k]);
            minc = min(minc, s_minc[k]); maxc = max(maxc, s_maxc[k]);
        }
        g_hi[n] = hi;   g_lo[n] = lo;
        g_minr[n] = minr; g_maxr[n] = maxr;
        g_minc[n] = minc; g_maxc[n] = maxc;
    }
}

// ============================================================
// Kernel 2: stability filter + stable-sort rank + greedy NMS.
// Single block, 1024 threads (thread j <-> mask j and sorted slot j).
// Writes keep + boxes to output, gated score to scratch.
// ============================================================
__global__ void __launch_bounds__(1024) sam_nms_kernel(const float* __restrict__ iou_preds,
                                                       float* __restrict__ out)
{
    const int j = threadIdx.x;

    __shared__ float s_key[NM];
    __shared__ float s_bl[NM], s_bt[NM], s_br[NM], s_bb[NM];  // sorted boxes
    __shared__ unsigned char s_keep[NM];                       // sorted-domain keep

    const float score = iou_preds[j];
    const float hi = (float)g_hi[j];
    const float lo = (float)g_lo[j];
    const float stability = hi / fmaxf(lo, 1.0f);

    const int minr = g_minr[j], maxr = g_maxr[j];
    const int minc = g_minc[j], maxc = g_maxc[j];
    const bool empty = (maxr < 0);
    const float bl = empty ? 0.0f : (float)minc;
    const float bt = empty ? 0.0f : (float)minr;
    const float br = empty ? 0.0f : (float)maxc;
    const float bb = empty ? 0.0f : (float)maxr;

    const bool valid = (score > 0.88f) && (stability >= 0.95f);

    s_key[j] = valid ? score : -INFINITY;
    __syncthreads();

    // stable descending rank (matches stable argsort of -key)
    // also count valid entries (keys != -inf) redundantly in each thread
    const float myk = s_key[j];
    int rank = 0;
    int nvalid = 0;
    for (int k = 0; k < NM; ++k) {
        const float kk = s_key[k];
        rank += (kk > myk) || ((kk == myk) && (k < j));
        nvalid += (kk != -INFINITY);
    }
    __syncthreads();  // all reads of s_key done before smem reuse below

    // scatter into sorted domain
    s_bl[rank] = bl; s_bt[rank] = bt; s_br[rank] = br; s_bb[rank] = bb;
    s_keep[rank] = valid ? 1 : 0;
    __syncthreads();

    // thread j now owns sorted slot j
    const float tl = s_bl[j], tt = s_bt[j], tr = s_br[j], tb = s_bb[j];
    const float myArea = fmaxf(tr - tl, 0.0f) * fmaxf(tb - tt, 0.0f);

    for (int i = 0; i < nvalid; ++i) {
        __syncthreads();
        if (!s_keep[i]) continue;           // uniform branch (shared value)
        if (j > i && s_keep[j]) {
            const float il = s_bl[i], it_ = s_bt[i], ir = s_br[i], ib = s_bb[i];
            const float x0 = fmaxf(il, tl), y0 = fmaxf(it_, tt);
            const float x1 = fminf(ir, tr), y1 = fminf(ib, tb);
            const float inter = fmaxf(x1 - x0, 0.0f) * fmaxf(y1 - y0, 0.0f);
            const float areaI = fmaxf(ir - il, 0.0f) * fmaxf(ib - it_, 0.0f);
            const float uni = fmaxf(areaI + myArea - inter, 1e-6f);
            if (inter / uni > 0.7f) s_keep[j] = 0;
        }
    }
    __syncthreads();

    const bool kept = (s_keep[rank] != 0);
    const float gated = kept ? score : 0.0f;
    g_gated[j] = gated;

    out[OUT_KEEP_OFF + j] = kept ? 1.0f : 0.0f;
    float* ob = out + OUT_BOX_OFF + (size_t)j * 4;
    ob[0] = bl; ob[1] = bt; ob[2] = br; ob[3] = bb;
}

// ============================================================
// Kernel 3: out = sigmoid(logits) * gated[n]; zero fast-path.
// 4096 blocks, each handles a quarter of one mask (16384 elems).
// ============================================================
__global__ void __launch_bounds__(256) sam_out_kernel(const float* __restrict__ logits,
                                                      float* __restrict__ out)
{
    const int n = blockIdx.x >> 2;
    const int q = blockIdx.x & 3;
    const float g = g_gated[n];

    const size_t base4 = (size_t)n * (HW / 4) + (size_t)q * (HW / 16);
    const float4* __restrict__ in4 = reinterpret_cast<const float4*>(logits) + base4;
    float4* __restrict__ o4 = reinterpret_cast<float4*>(out) + base4;
    const int tid = threadIdx.x;

    if (g == 0.0f) {
        const float4 z = make_float4(0.0f, 0.0f, 0.0f, 0.0f);
#pragma unroll
        for (int it = 0; it < 16; ++it)
            o4[it * 256 + tid] = z;
    } else {
#pragma unroll 4
        for (int it = 0; it < 16; ++it) {
            float4 v = in4[it * 256 + tid];
            v.x = g / (1.0f + __expf(-v.x));
            v.y = g / (1.0f + __expf(-v.y));
            v.z = g / (1.0f + __expf(-v.z));
            v.w = g / (1.0f + __expf(-v.w));
            o4[it * 256 + tid] = v;
        }
    }
}

extern "C" void kernel_launch(void* const* d_in, const int* in_sizes, int n_in,
                              void* d_out, int out_size)
{
    const float* logits    = (const float*)d_in[0];  // [1024,256,256]
    const float* iou_preds = (const float*)d_in[1];  // [1024]
    float* out = (float*)d_out;

    sam_stats_kernel<<<NM, 256>>>(logits);
    sam_nms_kernel<<<1, 1024>>>(iou_preds, out);
    sam_out_kernel<<<NM * 4, 256>>>(logits, out);
}

// round 4
// speedup vs baseline: 1.2556x; 1.2556x over previous
#include <cuda_runtime.h>
#include <math.h>

#define NM 1024
#define HH 256
#define WW 256
#define HW 65536
#define OUT_MASKS ((size_t)NM * HW)            // 67108864 floats
#define OUT_KEEP_OFF OUT_MASKS                 // keep[1024]
#define OUT_BOX_OFF (OUT_MASKS + NM)           // boxes[1024*4]

#define IOU_THRESH 0.88f

// ---- scratch (no allocations allowed) ----
__device__ int   g_hi[NM];
__device__ int   g_lo[NM];
__device__ int   g_minr[NM];
__device__ int   g_maxr[NM];
__device__ int   g_minc[NM];
__device__ int   g_maxc[NM];
__device__ float g_gated[NM];

// ============================================================
// Kernel 1 (fused): per-mask stats + zero-fill of output tiles
// for masks that fail the iou threshold (independent work,
// overlapped so reads and writes share the DRAM pipe).
//   blocks [0, NM)            : stats, one block per mask
//   blocks [NM, NM + 4*NM)    : zero-fill quarter-mask tiles
// ============================================================
__global__ void __launch_bounds__(256) sam_fused_kernel(const float* __restrict__ logits,
                                                        const float* __restrict__ iou_preds,
                                                        float* __restrict__ out)
{
    const int tid = threadIdx.x;

    if (blockIdx.x >= NM) {
        // ---- zero-fill path ----
        const int b = blockIdx.x - NM;
        const int n = b >> 2;
        const int q = b & 3;
        if (iou_preds[n] > IOU_THRESH) return;   // handled by out-kernel later
        float4* __restrict__ o4 = reinterpret_cast<float4*>(out)
                                + (size_t)n * (HW / 4) + (size_t)q * (HW / 16);
        const float4 z = make_float4(0.0f, 0.0f, 0.0f, 0.0f);
#pragma unroll
        for (int it = 0; it < 16; ++it)
            o4[it * 256 + tid] = z;
        return;
    }

    // ---- stats path ----
    const int n = blockIdx.x;
    const float4* __restrict__ p =
        reinterpret_cast<const float4*>(logits + (size_t)n * HW);

    int hi = 0, lo = 0;
    int minr = HH, maxr = -1, minc = WW, maxc = -1;

    // 65536 elems = 16384 float4; 256 threads -> 64 iters
#pragma unroll 8
    for (int it = 0; it < 64; ++it) {
        const int i4 = it * 256 + tid;
        const float4 v = p[i4];
        const int e   = i4 << 2;
        const int row = e >> 8;
        const int col = e & 255;

        const float vs0 = v.x, vs1 = v.y, vs2 = v.z, vs3 = v.w;
        hi += (vs0 > 1.0f) + (vs1 > 1.0f) + (vs2 > 1.0f) + (vs3 > 1.0f);
        lo += (vs0 > -1.0f) + (vs1 > -1.0f) + (vs2 > -1.0f) + (vs3 > -1.0f);

        const bool b0 = vs0 > 0.0f, b1 = vs1 > 0.0f, b2 = vs2 > 0.0f, b3 = vs3 > 0.0f;
        if (b0 | b1 | b2 | b3) {
            minr = min(minr, row);
            maxr = max(maxr, row);
            if (b0) { minc = min(minc, col);     maxc = max(maxc, col);     }
            if (b1) { minc = min(minc, col + 1); maxc = max(maxc, col + 1); }
            if (b2) { minc = min(minc, col + 2); maxc = max(maxc, col + 2); }
            if (b3) { minc = min(minc, col + 3); maxc = max(maxc, col + 3); }
        }
    }

    // warp reduce
#pragma unroll
    for (int o = 16; o > 0; o >>= 1) {
        hi   += __shfl_down_sync(0xFFFFFFFFu, hi, o);
        lo   += __shfl_down_sync(0xFFFFFFFFu, lo, o);
        minr = min(minr, __shfl_down_sync(0xFFFFFFFFu, minr, o));
        maxr = max(maxr, __shfl_down_sync(0xFFFFFFFFu, maxr, o));
        minc = min(minc, __shfl_down_sync(0xFFFFFFFFu, minc, o));
        maxc = max(maxc, __shfl_down_sync(0xFFFFFFFFu, maxc, o));
    }

    __shared__ int s_hi[8], s_lo[8], s_minr[8], s_maxr[8], s_minc[8], s_maxc[8];
    const int w = tid >> 5;
    if ((tid & 31) == 0) {
        s_hi[w] = hi; s_lo[w] = lo;
        s_minr[w] = minr; s_maxr[w] = maxr;
        s_minc[w] = minc; s_maxc[w] = maxc;
    }
    __syncthreads();
    if (tid == 0) {
#pragma unroll
        for (int k = 1; k < 8; ++k) {
            hi += s_hi[k]; lo += s_lo[k];
            minr = min(minr, s_minr[k]); maxr = max(maxr, s_maxr[k]);
            minc = min(minc, s_minc[k]); maxc = max(maxc, s_maxc[k]);
        }
        g_hi[n] = hi;   g_lo[n] = lo;
        g_minr[n] = minr; g_maxr[n] = maxr;
        g_minc[n] = minc; g_maxc[n] = maxc;
    }
}

// ============================================================
// Kernel 2: stability filter + compaction + rank + greedy NMS.
// Single block, 1024 threads. Only ~nvalid (~100) entries are
// compacted; rank scan and NMS loop run over nvalid, not 1024.
// ============================================================
__global__ void __launch_bounds__(1024) sam_nms_kernel(const float* __restrict__ iou_preds,
                                                       float* __restrict__ out)
{
    const int j = threadIdx.x;
    const int wid = j >> 5;
    const unsigned lane_lt = (1u << (j & 31)) - 1u;

    __shared__ int   s_wcnt[32];
    __shared__ float s_ckey[NM];     // compact keys (scores of valid)
    __shared__ int   s_cidx[NM];     // compact original indices
    __shared__ float s_sl[NM], s_st[NM], s_sr[NM], s_sb[NM];  // sorted boxes
    __shared__ unsigned char s_keep[NM];

    const float score = iou_preds[j];
    const float hi = (float)g_hi[j];
    const float lo = (float)g_lo[j];
    const float stability = hi / fmaxf(lo, 1.0f);

    const int minr = g_minr[j], maxr = g_maxr[j];
    const int minc = g_minc[j], maxc = g_maxc[j];
    const bool empty = (maxr < 0);
    const float bl = empty ? 0.0f : (float)minc;
    const float bt = empty ? 0.0f : (float)minr;
    const float br = empty ? 0.0f : (float)maxc;
    const float bb = empty ? 0.0f : (float)maxr;

    const bool valid = (score > IOU_THRESH) && (stability >= 0.95f);

    // ---- stable compaction of valid entries ----
    const unsigned ballot = __ballot_sync(0xFFFFFFFFu, valid);
    if ((j & 31) == 0) s_wcnt[wid] = __popc(ballot);
    __syncthreads();

    int warp_off = 0, nvalid = 0;
#pragma unroll
    for (int k = 0; k < 32; ++k) {
        const int c = s_wcnt[k];
        if (k < wid) warp_off += c;
        nvalid += c;
    }
    const int cpos = warp_off + __popc(ballot & lane_lt);  // compact slot (valid only)

    if (valid) {
        s_ckey[cpos] = score;
        s_cidx[cpos] = j;
    }
    __syncthreads();

    // ---- stable descending rank among valid entries only ----
    int rank = 0;
    if (valid) {
        for (int i = 0; i < nvalid; ++i) {
            const float kk = s_ckey[i];
            rank += (kk > score) || ((kk == score) && (s_cidx[i] < j));
        }
        // scatter into sorted domain (distinct slots, no sync needed before writes)
        s_sl[rank] = bl; s_st[rank] = bt; s_sr[rank] = br; s_sb[rank] = bb;
        s_keep[rank] = 1;
    }
    __syncthreads();

    // ---- greedy NMS over sorted valid entries ----
    float tl = 0.f, tt = 0.f, tr = 0.f, tb = 0.f, myArea = 0.f;
    if (j < nvalid) {
        tl = s_sl[j]; tt = s_st[j]; tr = s_sr[j]; tb = s_sb[j];
        myArea = fmaxf(tr - tl, 0.0f) * fmaxf(tb - tt, 0.0f);
    }

    for (int i = 0; i < nvalid; ++i) {
        __syncthreads();
        if (!s_keep[i]) continue;           // uniform branch (shared value)
        if (j > i && j < nvalid && s_keep[j]) {
            const float il = s_sl[i], it_ = s_st[i], ir = s_sr[i], ib = s_sb[i];
            const float x0 = fmaxf(il, tl), y0 = fmaxf(it_, tt);
            const float x1 = fminf(ir, tr), y1 = fminf(ib, tb);
            const float inter = fmaxf(x1 - x0, 0.0f) * fmaxf(y1 - y0, 0.0f);
            const float areaI = fmaxf(ir - il, 0.0f) * fmaxf(ib - it_, 0.0f);
            const float uni = fmaxf(areaI + myArea - inter, 1e-6f);
            if (inter / uni > 0.7f) s_keep[j] = 0;
        }
    }
    __syncthreads();

    const bool kept = valid && (s_keep[rank] != 0);
    g_gated[j] = kept ? score : 0.0f;

    out[OUT_KEEP_OFF + j] = kept ? 1.0f : 0.0f;
    float* ob = out + OUT_BOX_OFF + (size_t)j * 4;
    ob[0] = bl; ob[1] = bt; ob[2] = br; ob[3] = bb;
}

// ============================================================
// Kernel 3: only masks with iou > 0.88 (rest already zeroed).
// gated==0 -> zero store; else sigmoid*g.
// ============================================================
__global__ void __launch_bounds__(256) sam_out_kernel(const float* __restrict__ logits,
                                                      const float* __restrict__ iou_preds,
                                                      float* __restrict__ out)
{
    const int n = blockIdx.x >> 2;
    if (iou_preds[n] <= IOU_THRESH) return;   // already zeroed in fused kernel
    const int q = blockIdx.x & 3;
    const float g = g_gated[n];

    const size_t base4 = (size_t)n * (HW / 4) + (size_t)q * (HW / 16);
    const float4* __restrict__ in4 = reinterpret_cast<const float4*>(logits) + base4;
    float4* __restrict__ o4 = reinterpret_cast<float4*>(out) + base4;
    const int tid = threadIdx.x;

    if (g == 0.0f) {
        const float4 z = make_float4(0.0f, 0.0f, 0.0f, 0.0f);
#pragma unroll
        for (int it = 0; it < 16; ++it)
            o4[it * 256 + tid] = z;
    } else {
#pragma unroll 4
        for (int it = 0; it < 16; ++it) {
            float4 v = in4[it * 256 + tid];
            v.x = g / (1.0f + __expf(-v.x));
            v.y = g / (1.0f + __expf(-v.y));
            v.z = g / (1.0f + __expf(-v.z));
            v.w = g / (1.0f + __expf(-v.w));
            o4[it * 256 + tid] = v;
        }
    }
}

extern "C" void kernel_launch(void* const* d_in, const int* in_sizes, int n_in,
                              void* d_out, int out_size)
{
    const float* logits    = (const float*)d_in[0];  // [1024,256,256]
    const float* iou_preds = (const float*)d_in[1];  // [1024]
    float* out = (float*)d_out;

    sam_fused_kernel<<<NM + NM * 4, 256>>>(logits, iou_preds, out);
    sam_nms_kernel<<<1, 1024>>>(iou_preds, out);
    sam_out_kernel<<<NM * 4, 256>>>(logits, iou_preds, out);
}